// round 1
// baseline (speedup 1.0000x reference)
#include <cuda_runtime.h>
#include <math.h>

#define Hh    56
#define Wd    56
#define WS    7
#define SHIFT 3
#define HEADS 4
#define DIM   128
#define HD    32
#define NMLP  512
#define BATCH 64
#define L     (Hh*Wd)          /* 3136 */
#define NWIN  64               /* windows per batch */
#define TOTWIN (BATCH*NWIN)    /* 4096 */
#define M_TOK (BATCH*L)        /* 200704 */
#define WSQ   49
#define AS_LD 132              /* padded A-tile row stride */

/* ---------------- scratch (device globals; no allocation allowed) ------- */
__device__ float g_xs  [M_TOK*DIM];                    /* LN1 output      */
__device__ float g_gate[BATCH];                        /* ECA gates       */
__device__ float g_qkv [TOTWIN*3*HEADS*WSQ*HD];        /* [win][3][h][49][32] */
__device__ float g_awin[TOTWIN*WSQ*DIM];               /* attn out, window order */
__device__ float g_x2  [M_TOK*DIM];                    /* after residual 1 */
__device__ float g_xn  [M_TOK*DIM];                    /* LN2 output      */

/* ---------------- mapping: window row m -> original token --------------- */
__device__ __forceinline__ int win_src_token(int m, int* pb) {
    int win = m / WSQ, t = m - win * WSQ;
    int b = win >> 6, widx = win & 63;
    int wh = widx >> 3, ww = widx & 7;
    int i = t / WS, j = t - i * WS;
    int sh = wh * WS + i, sw = ww * WS + j;
    int h = sh + SHIFT; if (h >= Hh) h -= Hh;
    int w = sw + SHIFT; if (w >= Wd) w -= Wd;
    if (pb) *pb = b;
    return b * L + h * Wd + w;
}

/* ---------------- LayerNorm (one 128-thread block per token) ------------ */
__global__ void k_ln(const float* __restrict__ x, const float* __restrict__ g,
                     const float* __restrict__ b, float* __restrict__ o) {
    int tok = blockIdx.x;
    int c = threadIdx.x;
    float v = x[(size_t)tok * DIM + c];
    __shared__ float red[4];
    float s = v;
    #pragma unroll
    for (int off = 16; off; off >>= 1) s += __shfl_xor_sync(0xffffffffu, s, off);
    if ((c & 31) == 0) red[c >> 5] = s;
    __syncthreads();
    float mu = (red[0] + red[1] + red[2] + red[3]) * (1.0f / DIM);
    float d = v - mu;
    float s2 = d * d;
    #pragma unroll
    for (int off = 16; off; off >>= 1) s2 += __shfl_xor_sync(0xffffffffu, s2, off);
    __syncthreads();
    if ((c & 31) == 0) red[c >> 5] = s2;
    __syncthreads();
    float var = (red[0] + red[1] + red[2] + red[3]) * (1.0f / DIM);
    o[(size_t)tok * DIM + c] = d * rsqrtf(var + 1e-5f) * g[c] + b[c];
}

/* ---------------- ECA gate: mean over L of xs, dot with center tap ------ */
__global__ void k_gate(const float* __restrict__ xs, const float* __restrict__ eca_w,
                       float* __restrict__ gate) {
    int b = blockIdx.x;
    int tid = threadIdx.x;           /* 512 threads */
    int c = tid & 127, lg = tid >> 7;
    const float* p = xs + ((size_t)b * L + (size_t)lg * 784) * DIM + c;
    float s = 0.f;
    for (int l = 0; l < 784; l++) s += p[(size_t)l * DIM];
    __shared__ float part[4][128];
    __shared__ float valbuf[128];
    part[lg][c] = s;
    __syncthreads();
    if (tid < 128) {
        float tot = part[0][c] + part[1][c] + part[2][c] + part[3][c];
        valbuf[c] = (tot * (1.0f / L)) * eca_w[DIM + c];  /* center tap [1][c][0] */
    }
    __syncthreads();
    if (tid == 0) {
        float a = 0.f;
        for (int i = 0; i < 128; i++) a += valbuf[i];
        gate[b] = 1.0f / (1.0f + expf(-a));
    }
}

/* ---------------- QKV GEMM with shifted-window gather ------------------- */
/* grid (3136, 6), 256 thr, 64x64 tile, full K=128 resident                  */
__global__ void k_qkv(const float* __restrict__ xs, const float* __restrict__ w,
                      const float* __restrict__ bias, float* __restrict__ qkv) {
    extern __shared__ float sm[];
    float* As = sm;                 /* [64][AS_LD] */
    float* Bs = sm + 64 * AS_LD;    /* [128][64]   */
    __shared__ int srow[64];
    int tid = threadIdx.x;
    int m0 = blockIdx.x * 64, n0 = blockIdx.y * 64;
    if (tid < 64) srow[tid] = win_src_token(m0 + tid, 0);
    __syncthreads();
    {
        int r = tid >> 5, k4 = (tid & 31) << 2;
        #pragma unroll
        for (int p = 0; p < 8; p++) {
            int row = (p << 3) + r;
            float4 v = *(const float4*)(xs + (size_t)srow[row] * DIM + k4);
            *(float4*)(As + row * AS_LD + k4) = v;
        }
    }
    {
        int kq = tid >> 4, c4 = (tid & 15) << 2;
        #pragma unroll
        for (int p = 0; p < 8; p++) {
            int kk = (p << 4) + kq;
            *(float4*)(Bs + kk * 64 + c4) = *(const float4*)(w + (size_t)kk * 384 + n0 + c4);
        }
    }
    __syncthreads();
    int ty = tid >> 4, tx = tid & 15;
    float acc[4][4];
    #pragma unroll
    for (int i = 0; i < 4; i++)
        #pragma unroll
        for (int j = 0; j < 4; j++) acc[i][j] = 0.f;
    const float* ap = As + (ty * 4) * AS_LD;
    const float* bp = Bs + tx * 4;
    #pragma unroll 8
    for (int k = 0; k < 128; k++) {
        float a0 = ap[k], a1 = ap[AS_LD + k], a2 = ap[2 * AS_LD + k], a3 = ap[3 * AS_LD + k];
        float4 bv = *(const float4*)(bp + k * 64);
        acc[0][0] += a0 * bv.x; acc[0][1] += a0 * bv.y; acc[0][2] += a0 * bv.z; acc[0][3] += a0 * bv.w;
        acc[1][0] += a1 * bv.x; acc[1][1] += a1 * bv.y; acc[1][2] += a1 * bv.z; acc[1][3] += a1 * bv.w;
        acc[2][0] += a2 * bv.x; acc[2][1] += a2 * bv.y; acc[2][2] += a2 * bv.z; acc[2][3] += a2 * bv.w;
        acc[3][0] += a3 * bv.x; acc[3][1] += a3 * bv.y; acc[3][2] += a3 * bv.z; acc[3][3] += a3 * bv.w;
    }
    #pragma unroll
    for (int ii = 0; ii < 4; ii++) {
        int m = m0 + ty * 4 + ii;
        int win = m / WSQ, t = m - win * WSQ;
        #pragma unroll
        for (int jj = 0; jj < 4; jj++) {
            int n = n0 + tx * 4 + jj;
            int which = n >> 7, rem = n & 127;
            int head = rem >> 5, d = rem & 31;
            qkv[(((size_t)win * 3 + which) * HEADS + head) * (WSQ * HD) + t * HD + d]
                = acc[ii][jj] + bias[n];
        }
    }
}

/* ---------------- window attention: one block per (window, head) -------- */
__global__ void k_attn(const float* __restrict__ qkv, const float* __restrict__ tbl,
                       const int* __restrict__ ridx, const float* __restrict__ mask,
                       float* __restrict__ awin) {
    int win = blockIdx.x, head = blockIdx.y;
    int widx = win & 63;
    __shared__ float qs[WSQ * HD], ks[WSQ * HD], vs[WSQ * HD];
    __shared__ float att[WSQ * 50];
    int tid = threadIdx.x;          /* 256 */
    const float scale = 0.17677669529663687f; /* 32^-0.5 */
    size_t base = ((size_t)win * 3 * HEADS + head) * (WSQ * HD);
    size_t stride = (size_t)HEADS * WSQ * HD;
    for (int e = tid; e < WSQ * HD; e += 256) {
        qs[e] = qkv[base + e] * scale;
        ks[e] = qkv[base + stride + e];
        vs[e] = qkv[base + 2 * stride + e];
    }
    __syncthreads();
    const float* mrow = mask + (size_t)widx * WSQ * WSQ;
    for (int e = tid; e < WSQ * WSQ; e += 256) {
        int i = e / WSQ, j = e - i * WSQ;
        const float* qp = qs + i * HD;
        const float* kp = ks + j * HD;
        float s = 0.f;
        #pragma unroll
        for (int d = 0; d < HD; d++) s += qp[d] * kp[d];
        s += tbl[ridx[e] * HEADS + head] + mrow[e];
        att[i * 50 + j] = s;
    }
    __syncthreads();
    if (tid < WSQ) {
        float* r = att + tid * 50;
        float mx = r[0];
        for (int j = 1; j < WSQ; j++) mx = fmaxf(mx, r[j]);
        float sum = 0.f;
        for (int j = 0; j < WSQ; j++) { float e_ = __expf(r[j] - mx); r[j] = e_; sum += e_; }
        float inv = 1.0f / sum;
        for (int j = 0; j < WSQ; j++) r[j] *= inv;
    }
    __syncthreads();
    for (int e = tid; e < WSQ * HD; e += 256) {
        int i = e >> 5, d = e & 31;
        const float* r = att + i * 50;
        float s = 0.f;
        #pragma unroll
        for (int j = 0; j < WSQ; j++) s += r[j] * vs[j * HD + d];
        awin[((size_t)win * WSQ + i) * DIM + head * HD + d] = s;
    }
}

/* ---------------- proj GEMM + window-reverse + residual + cattn --------- */
__global__ void k_proj(const float* __restrict__ awin, const float* __restrict__ w,
                       const float* __restrict__ bias, const float* __restrict__ x,
                       const float* __restrict__ xs, const float* __restrict__ gate,
                       float* __restrict__ x2) {
    extern __shared__ float sm[];
    float* As = sm;
    float* Bs = sm + 64 * AS_LD;
    int tid = threadIdx.x;
    int m0 = blockIdx.x * 64, n0 = blockIdx.y * 64;
    {
        int r = tid >> 5, k4 = (tid & 31) << 2;
        #pragma unroll
        for (int p = 0; p < 8; p++) {
            int row = (p << 3) + r;
            *(float4*)(As + row * AS_LD + k4) =
                *(const float4*)(awin + (size_t)(m0 + row) * DIM + k4);
        }
    }
    {
        int kq = tid >> 4, c4 = (tid & 15) << 2;
        #pragma unroll
        for (int p = 0; p < 8; p++) {
            int kk = (p << 4) + kq;
            *(float4*)(Bs + kk * 64 + c4) = *(const float4*)(w + (size_t)kk * DIM + n0 + c4);
        }
    }
    __syncthreads();
    int ty = tid >> 4, tx = tid & 15;
    float acc[4][4];
    #pragma unroll
    for (int i = 0; i < 4; i++)
        #pragma unroll
        for (int j = 0; j < 4; j++) acc[i][j] = 0.f;
    const float* ap = As + (ty * 4) * AS_LD;
    const float* bp = Bs + tx * 4;
    #pragma unroll 8
    for (int k = 0; k < 128; k++) {
        float a0 = ap[k], a1 = ap[AS_LD + k], a2 = ap[2 * AS_LD + k], a3 = ap[3 * AS_LD + k];
        float4 bv = *(const float4*)(bp + k * 64);
        acc[0][0] += a0 * bv.x; acc[0][1] += a0 * bv.y; acc[0][2] += a0 * bv.z; acc[0][3] += a0 * bv.w;
        acc[1][0] += a1 * bv.x; acc[1][1] += a1 * bv.y; acc[1][2] += a1 * bv.z; acc[1][3] += a1 * bv.w;
        acc[2][0] += a2 * bv.x; acc[2][1] += a2 * bv.y; acc[2][2] += a2 * bv.z; acc[2][3] += a2 * bv.w;
        acc[3][0] += a3 * bv.x; acc[3][1] += a3 * bv.y; acc[3][2] += a3 * bv.z; acc[3][3] += a3 * bv.w;
    }
    #pragma unroll
    for (int ii = 0; ii < 4; ii++) {
        int m = m0 + ty * 4 + ii;
        int bb;
        int dst = win_src_token(m, &bb);
        float gt = gate[bb];
        #pragma unroll
        for (int jj = 0; jj < 4; jj++) {
            int n = n0 + tx * 4 + jj;
            size_t off = (size_t)dst * DIM + n;
            x2[off] = x[off] + xs[off] * gt + acc[ii][jj] + bias[n];
        }
    }
}

/* ---------------- fused MLP: 64 tokens/block, N chunked by 128 ---------- */
__global__ void k_mlp(const float* __restrict__ xn, const float* __restrict__ w1,
                      const float* __restrict__ b1, const float* __restrict__ w2,
                      const float* __restrict__ b2, const float* __restrict__ x2,
                      float* __restrict__ out) {
    extern __shared__ float sm[];
    float* xns = sm;                 /* 64*128  */
    float* h1s = sm + 8192;          /* 64*128  */
    float* w1s = sm + 16384;         /* 128*128 */
    float* w2s = sm + 32768;         /* 128*128 */
    int tid = threadIdx.x;           /* 256 */
    size_t t0 = (size_t)blockIdx.x * 64;
    {
        const float4* src = (const float4*)(xn + t0 * DIM);
        float4* dst = (float4*)xns;
        #pragma unroll
        for (int p = 0; p < 8; p++) dst[p * 256 + tid] = src[p * 256 + tid];
    }
    int tg = tid >> 4;   /* token group: tokens tg*4..+3 */
    int cg = tid & 15;   /* col group:   cols  cg*8..+7  */
    float acc[4][8];
    #pragma unroll
    for (int i = 0; i < 4; i++)
        #pragma unroll
        for (int q = 0; q < 8; q++) acc[i][q] = 0.f;

    for (int cc = 0; cc < 4; cc++) {
        __syncthreads();  /* also covers xns load on first iteration */
        #pragma unroll
        for (int p = 0; p < 16; p++) {
            int q = p * 256 + tid;
            int k = q >> 5, n4 = (q & 31) << 2;
            *(float4*)(w1s + k * 128 + n4) =
                *(const float4*)(w1 + (size_t)k * NMLP + cc * 128 + n4);
        }
        {
            const float4* src = (const float4*)(w2 + (size_t)cc * 128 * DIM);
            float4* dst = (float4*)w2s;
            #pragma unroll
            for (int p = 0; p < 16; p++) dst[p * 256 + tid] = src[p * 256 + tid];
        }
        __syncthreads();

        /* phase 1: h1 = gelu(xn @ w1chunk + b1) */
        float hacc[4][8];
        #pragma unroll
        for (int i = 0; i < 4; i++)
            #pragma unroll
            for (int q = 0; q < 8; q++) hacc[i][q] = b1[cc * 128 + cg * 8 + q];
        #pragma unroll 4
        for (int k = 0; k < 128; k++) {
            float xv0 = xns[(tg * 4 + 0) * 128 + k];
            float xv1 = xns[(tg * 4 + 1) * 128 + k];
            float xv2 = xns[(tg * 4 + 2) * 128 + k];
            float xv3 = xns[(tg * 4 + 3) * 128 + k];
            float4 wA = *(const float4*)(w1s + k * 128 + cg * 8);
            float4 wB = *(const float4*)(w1s + k * 128 + cg * 8 + 4);
            hacc[0][0] += xv0 * wA.x; hacc[0][1] += xv0 * wA.y; hacc[0][2] += xv0 * wA.z; hacc[0][3] += xv0 * wA.w;
            hacc[0][4] += xv0 * wB.x; hacc[0][5] += xv0 * wB.y; hacc[0][6] += xv0 * wB.z; hacc[0][7] += xv0 * wB.w;
            hacc[1][0] += xv1 * wA.x; hacc[1][1] += xv1 * wA.y; hacc[1][2] += xv1 * wA.z; hacc[1][3] += xv1 * wA.w;
            hacc[1][4] += xv1 * wB.x; hacc[1][5] += xv1 * wB.y; hacc[1][6] += xv1 * wB.z; hacc[1][7] += xv1 * wB.w;
            hacc[2][0] += xv2 * wA.x; hacc[2][1] += xv2 * wA.y; hacc[2][2] += xv2 * wA.z; hacc[2][3] += xv2 * wA.w;
            hacc[2][4] += xv2 * wB.x; hacc[2][5] += xv2 * wB.y; hacc[2][6] += xv2 * wB.z; hacc[2][7] += xv2 * wB.w;
            hacc[3][0] += xv3 * wA.x; hacc[3][1] += xv3 * wA.y; hacc[3][2] += xv3 * wA.z; hacc[3][3] += xv3 * wA.w;
            hacc[3][4] += xv3 * wB.x; hacc[3][5] += xv3 * wB.y; hacc[3][6] += xv3 * wB.z; hacc[3][7] += xv3 * wB.w;
        }
        #pragma unroll
        for (int i = 0; i < 4; i++)
            #pragma unroll
            for (int q = 0; q < 8; q++) {
                float hv = hacc[i][q];
                h1s[(tg * 4 + i) * 128 + cg * 8 + q] =
                    0.5f * hv * (1.0f + erff(hv * 0.70710678118654752f));
            }
        __syncthreads();

        /* phase 2: acc += gelu(h1) @ w2chunk */
        #pragma unroll 4
        for (int n = 0; n < 128; n++) {
            float h0 = h1s[(tg * 4 + 0) * 128 + n];
            float h1 = h1s[(tg * 4 + 1) * 128 + n];
            float h2 = h1s[(tg * 4 + 2) * 128 + n];
            float h3 = h1s[(tg * 4 + 3) * 128 + n];
            float4 wA = *(const float4*)(w2s + n * 128 + cg * 8);
            float4 wB = *(const float4*)(w2s + n * 128 + cg * 8 + 4);
            acc[0][0] += h0 * wA.x; acc[0][1] += h0 * wA.y; acc[0][2] += h0 * wA.z; acc[0][3] += h0 * wA.w;
            acc[0][4] += h0 * wB.x; acc[0][5] += h0 * wB.y; acc[0][6] += h0 * wB.z; acc[0][7] += h0 * wB.w;
            acc[1][0] += h1 * wA.x; acc[1][1] += h1 * wA.y; acc[1][2] += h1 * wA.z; acc[1][3] += h1 * wA.w;
            acc[1][4] += h1 * wB.x; acc[1][5] += h1 * wB.y; acc[1][6] += h1 * wB.z; acc[1][7] += h1 * wB.w;
            acc[2][0] += h2 * wA.x; acc[2][1] += h2 * wA.y; acc[2][2] += h2 * wA.z; acc[2][3] += h2 * wA.w;
            acc[2][4] += h2 * wB.x; acc[2][5] += h2 * wB.y; acc[2][6] += h2 * wB.z; acc[2][7] += h2 * wB.w;
            acc[3][0] += h3 * wA.x; acc[3][1] += h3 * wA.y; acc[3][2] += h3 * wA.z; acc[3][3] += h3 * wA.w;
            acc[3][4] += h3 * wB.x; acc[3][5] += h3 * wB.y; acc[3][6] += h3 * wB.z; acc[3][7] += h3 * wB.w;
        }
    }
    #pragma unroll
    for (int i = 0; i < 4; i++) {
        size_t row = (t0 + tg * 4 + i) * DIM;
        #pragma unroll
        for (int q = 0; q < 8; q++) {
            int c = cg * 8 + q;
            out[row + c] = x2[row + c] + acc[i][q] + b2[c];
        }
    }
}

/* ------------------------------- launch --------------------------------- */
extern "C" void kernel_launch(void* const* d_in, const int* in_sizes, int n_in,
                              void* d_out, int out_size) {
    const float* x        = (const float*)d_in[0];
    const float* ln1_g    = (const float*)d_in[1];
    const float* ln1_b    = (const float*)d_in[2];
    const float* eca_w    = (const float*)d_in[3];
    const float* qkv_w    = (const float*)d_in[4];
    const float* qkv_b    = (const float*)d_in[5];
    const float* rel_tbl  = (const float*)d_in[6];
    const float* proj_w   = (const float*)d_in[7];
    const float* proj_b   = (const float*)d_in[8];
    const float* ln2_g    = (const float*)d_in[9];
    const float* ln2_b    = (const float*)d_in[10];
    const float* mlp_w1   = (const float*)d_in[11];
    const float* mlp_b1   = (const float*)d_in[12];
    const float* mlp_w2   = (const float*)d_in[13];
    const float* mlp_b2   = (const float*)d_in[14];
    const float* attn_msk = (const float*)d_in[15];
    const int*   rel_idx  = (const int*)d_in[16];
    float* out = (float*)d_out;

    float *xs_p, *gate_p, *qkv_p, *awin_p, *x2_p, *xn_p;
    cudaGetSymbolAddress((void**)&xs_p,   g_xs);
    cudaGetSymbolAddress((void**)&gate_p, g_gate);
    cudaGetSymbolAddress((void**)&qkv_p,  g_qkv);
    cudaGetSymbolAddress((void**)&awin_p, g_awin);
    cudaGetSymbolAddress((void**)&x2_p,   g_x2);
    cudaGetSymbolAddress((void**)&xn_p,   g_xn);

    const int SMEM_GEMM = (64 * AS_LD + 128 * 64) * 4;   /* 66560 B */
    const int SMEM_MLP  = 49152 * 4;                     /* 192 KB  */
    cudaFuncSetAttribute(k_qkv,  cudaFuncAttributeMaxDynamicSharedMemorySize, SMEM_GEMM);
    cudaFuncSetAttribute(k_proj, cudaFuncAttributeMaxDynamicSharedMemorySize, SMEM_GEMM);
    cudaFuncSetAttribute(k_mlp,  cudaFuncAttributeMaxDynamicSharedMemorySize, SMEM_MLP);

    k_ln  <<<M_TOK, 128>>>(x, ln1_g, ln1_b, xs_p);
    k_gate<<<BATCH, 512>>>(xs_p, eca_w, gate_p);
    k_qkv <<<dim3(M_TOK / 64, 6), 256, SMEM_GEMM>>>(xs_p, qkv_w, qkv_b, qkv_p);
    k_attn<<<dim3(TOTWIN, HEADS), 256>>>(qkv_p, rel_tbl, rel_idx, attn_msk, awin_p);
    k_proj<<<dim3(M_TOK / 64, 2), 256, SMEM_GEMM>>>(awin_p, proj_w, proj_b, x, xs_p, gate_p, x2_p);
    k_ln  <<<M_TOK, 128>>>(x2_p, ln2_g, ln2_b, xn_p);
    k_mlp <<<M_TOK / 64, 256, SMEM_MLP>>>(xn_p, mlp_w1, mlp_b1, mlp_w2, mlp_b2, x2_p, out);
}

// round 2
// speedup vs baseline: 4.0071x; 4.0071x over previous
#include <cuda_runtime.h>
#include <cuda_bf16.h>
#include <math.h>
#include <stdint.h>

#define Hh    56
#define Wd    56
#define WS    7
#define SHIFT 3
#define HEADS 4
#define DIM   128
#define HD    32
#define NMLP  512
#define BATCH 64
#define L     (Hh*Wd)
#define NWIN  64
#define TOTWIN (BATCH*NWIN)
#define M_TOK (BATCH*L)
#define WSQ   49

typedef __nv_bfloat16  bf16;
typedef __nv_bfloat162 bf162;

/* ---------------- scratch (device globals) ------------------------------ */
__device__ float g_xs  [M_TOK*DIM];
__device__ bf16  g_xsb [M_TOK*DIM];
__device__ float g_gate[BATCH];
__device__ bf16  g_qkvb[(size_t)TOTWIN*3*HEADS*WSQ*HD];
__device__ bf16  g_awinb[(size_t)M_TOK*DIM];
__device__ float g_x2  [M_TOK*DIM];
__device__ bf16  g_xnb [M_TOK*DIM];
__device__ bf16  g_wqb [DIM*3*DIM];
__device__ bf16  g_wpb [DIM*DIM];
__device__ bf16  g_w1b [DIM*NMLP];
__device__ bf16  g_w2b [NMLP*DIM];
__device__ float g_bm  [NWIN*HEADS*WSQ*56];

/* ---------------- small helpers ----------------------------------------- */
__device__ __forceinline__ uint32_t sptr(const void* p) {
    return (uint32_t)__cvta_generic_to_shared(p);
}
__device__ __forceinline__ void mma16816(float c[4], const uint32_t a[4], const uint32_t b[2]) {
    asm volatile("mma.sync.aligned.m16n8k16.row.col.f32.bf16.bf16.f32 "
                 "{%0,%1,%2,%3},{%4,%5,%6,%7},{%8,%9},{%0,%1,%2,%3};\n"
                 : "+f"(c[0]), "+f"(c[1]), "+f"(c[2]), "+f"(c[3])
                 : "r"(a[0]), "r"(a[1]), "r"(a[2]), "r"(a[3]), "r"(b[0]), "r"(b[1]));
}
__device__ __forceinline__ void ldsm4(uint32_t r[4], uint32_t addr) {
    asm volatile("ldmatrix.sync.aligned.m8n8.x4.shared.b16 {%0,%1,%2,%3},[%4];\n"
                 : "=r"(r[0]), "=r"(r[1]), "=r"(r[2]), "=r"(r[3]) : "r"(addr));
}
__device__ __forceinline__ void ldsm4t(uint32_t r[4], uint32_t addr) {
    asm volatile("ldmatrix.sync.aligned.m8n8.x4.trans.shared.b16 {%0,%1,%2,%3},[%4];\n"
                 : "=r"(r[0]), "=r"(r[1]), "=r"(r[2]), "=r"(r[3]) : "r"(addr));
}
/* A fragment 16x16 (row-major) at (row0,k0) */
__device__ __forceinline__ void load_afrag(uint32_t r[4], const bf16* As, int lda,
                                           int row0, int k0, int lane) {
    int q = lane >> 3, rr = lane & 7;
    int row = row0 + rr + ((q & 1) << 3);
    int col = k0 + ((q & 2) << 2);
    ldsm4(r, sptr(As + row * lda + col));
}
/* two adjacent B fragments (n0, n0+8) of 16k x 8n from row-major B[k][n] */
__device__ __forceinline__ void load_bfrag2(uint32_t r[4], const bf16* Bs, int ldb,
                                            int k0, int n0, int lane) {
    int q = lane >> 3, rr = lane & 7;
    int row = k0 + rr + ((q & 1) << 3);
    int col = n0 + ((q & 2) << 2);
    ldsm4t(r, sptr(Bs + row * ldb + col));
}
__device__ __forceinline__ uint32_t pack_bf2(float a, float b) {
    bf162 t = __floats2bfloat162_rn(a, b);
    return *(uint32_t*)&t;
}
__device__ __forceinline__ int win_src_token(int m, int* pb) {
    int win = m / WSQ, t = m - win * WSQ;
    int b = win >> 6, widx = win & 63;
    int wh = widx >> 3, ww = widx & 7;
    int i = t / WS, j = t - i * WS;
    int sh = wh * WS + i, sw = ww * WS + j;
    int h = sh + SHIFT; if (h >= Hh) h -= Hh;
    int w = sw + SHIFT; if (w >= Wd) w -= Wd;
    if (pb) *pb = b;
    return b * L + h * Wd + w;
}

/* ---------------- weight conversion + bias/mask precompute -------------- */
__global__ void k_convw(const float* __restrict__ qw, const float* __restrict__ pw,
                        const float* __restrict__ w1, const float* __restrict__ w2,
                        bf16* qwb, bf16* pwb, bf16* w1b, bf16* w2b) {
    int i = blockIdx.x * 256 + threadIdx.x;
    if (i < DIM * 3 * DIM) qwb[i] = __float2bfloat16(qw[i]);
    if (i < DIM * DIM)     pwb[i] = __float2bfloat16(pw[i]);
    if (i < DIM * NMLP) { w1b[i] = __float2bfloat16(w1[i]); w2b[i] = __float2bfloat16(w2[i]); }
}
__global__ void k_bm(const float* __restrict__ tbl, const int* __restrict__ ridx,
                     const float* __restrict__ mask, float* __restrict__ bm) {
    int idx = blockIdx.x * 256 + threadIdx.x;
    const int total = NWIN * HEADS * WSQ * 56;
    if (idx >= total) return;
    int j = idx % 56; int r = idx / 56;
    int i = r % WSQ; r /= WSQ;
    int h = r % HEADS; int widx = r / HEADS;
    float v = -1e30f;
    if (j < WSQ) v = tbl[ridx[i * WSQ + j] * HEADS + h] + mask[(size_t)widx * 2401 + i * WSQ + j];
    bm[idx] = v;
}

/* ---------------- LN1 (writes f32 + bf16) ------------------------------- */
__global__ void k_ln1(const float* __restrict__ x, const float* __restrict__ g,
                      const float* __restrict__ b, float* __restrict__ o,
                      bf16* __restrict__ ob) {
    int tok = blockIdx.x;
    int c = threadIdx.x;
    float v = x[(size_t)tok * DIM + c];
    __shared__ float red[4];
    float s = v;
    #pragma unroll
    for (int off = 16; off; off >>= 1) s += __shfl_xor_sync(0xffffffffu, s, off);
    if ((c & 31) == 0) red[c >> 5] = s;
    __syncthreads();
    float mu = (red[0] + red[1] + red[2] + red[3]) * (1.0f / DIM);
    float d = v - mu;
    float s2 = d * d;
    #pragma unroll
    for (int off = 16; off; off >>= 1) s2 += __shfl_xor_sync(0xffffffffu, s2, off);
    __syncthreads();
    if ((c & 31) == 0) red[c >> 5] = s2;
    __syncthreads();
    float var = (red[0] + red[1] + red[2] + red[3]) * (1.0f / DIM);
    float r = d * rsqrtf(var + 1e-5f) * g[c] + b[c];
    o[(size_t)tok * DIM + c]  = r;
    ob[(size_t)tok * DIM + c] = __float2bfloat16(r);
}

/* ---------------- ECA gate ---------------------------------------------- */
__global__ void k_gate(const float* __restrict__ xs, const float* __restrict__ eca_w,
                       float* __restrict__ gate) {
    int b = blockIdx.x;
    int tid = threadIdx.x;
    int c = tid & 127, lg = tid >> 7;
    const float* p = xs + ((size_t)b * L + (size_t)lg * 784) * DIM + c;
    float s = 0.f;
    for (int l = 0; l < 784; l++) s += p[(size_t)l * DIM];
    __shared__ float part[4][128];
    __shared__ float valbuf[128];
    part[lg][c] = s;
    __syncthreads();
    if (tid < 128) valbuf[c] = (part[0][c] + part[1][c] + part[2][c] + part[3][c]) * (1.0f / L) * eca_w[DIM + c];
    __syncthreads();
    if (tid == 0) {
        float a = 0.f;
        for (int i = 0; i < 128; i++) a += valbuf[i];
        gate[b] = 1.0f / (1.0f + expf(-a));
    }
}

/* ---------------- QKV GEMM (bf16 mma, gathered A) ------------------------ */
#define QLD 136
__global__ __launch_bounds__(256) void k_qkv(const bf16* __restrict__ xsb,
        const bf16* __restrict__ wqb, const float* __restrict__ qkv_b,
        bf16* __restrict__ qkvo) {
    extern __shared__ bf16 smq[];
    bf16* As = smq;                 /* [128][136] */
    bf16* Bs = smq + 128 * QLD;     /* [128][136] */
    __shared__ int srow[128];
    int tid = threadIdx.x;
    int m0 = blockIdx.x * 128, n0g = blockIdx.y * 128;
    if (tid < 128) srow[tid] = win_src_token(m0 + tid, 0);
    __syncthreads();
    for (int i = tid; i < 128 * 16; i += 256) {
        int r = i >> 4, c = i & 15;
        *(uint4*)(As + r * QLD + c * 8) = *(const uint4*)(xsb + (size_t)srow[r] * DIM + c * 8);
    }
    for (int i = tid; i < 128 * 16; i += 256) {
        int r = i >> 4, c = i & 15;
        *(uint4*)(Bs + r * QLD + c * 8) = *(const uint4*)(wqb + (size_t)r * 384 + n0g + c * 8);
    }
    __syncthreads();
    int warp = tid >> 5, lane = tid & 31;
    int wm0 = (warp & 3) * 32, wn0 = (warp >> 2) * 64;
    float acc[2][8][4];
    #pragma unroll
    for (int a = 0; a < 2; a++)
        #pragma unroll
        for (int b = 0; b < 8; b++)
            #pragma unroll
            for (int q = 0; q < 4; q++) acc[a][b][q] = 0.f;
    #pragma unroll
    for (int ks = 0; ks < 8; ks++) {
        int k0 = ks * 16;
        uint32_t af[2][4];
        load_afrag(af[0], As, QLD, wm0,      k0, lane);
        load_afrag(af[1], As, QLD, wm0 + 16, k0, lane);
        uint32_t bfr[8][2];
        #pragma unroll
        for (int nt = 0; nt < 4; nt++) {
            uint32_t t4[4];
            load_bfrag2(t4, Bs, QLD, k0, wn0 + nt * 16, lane);
            bfr[nt*2][0]=t4[0]; bfr[nt*2][1]=t4[1]; bfr[nt*2+1][0]=t4[2]; bfr[nt*2+1][1]=t4[3];
        }
        #pragma unroll
        for (int mi = 0; mi < 2; mi++)
            #pragma unroll
            for (int ni = 0; ni < 8; ni++) mma16816(acc[mi][ni], af[mi], bfr[ni]);
    }
    #pragma unroll
    for (int mi = 0; mi < 2; mi++) {
        int rbase = m0 + wm0 + mi * 16 + (lane >> 2);
        #pragma unroll
        for (int ni = 0; ni < 8; ni++) {
            int n = n0g + wn0 + ni * 8 + ((lane & 3) << 1);
            float b0 = qkv_b[n], b1 = qkv_b[n + 1];
            int which = n >> 7, rem = n & 127, head = rem >> 5, d = rem & 31;
            #pragma unroll
            for (int h2 = 0; h2 < 2; h2++) {
                int m = rbase + h2 * 8;
                int win = m / WSQ, t = m - win * WSQ;
                size_t off = ((((size_t)win * 3 + which) * HEADS + head) * WSQ + t) * HD + d;
                *(bf162*)(qkvo + off) =
                    __floats2bfloat162_rn(acc[mi][ni][h2*2] + b0, acc[mi][ni][h2*2+1] + b1);
            }
        }
    }
}

/* ---------------- window attention (flash-style mma) --------------------- */
#define ALD 40
__global__ __launch_bounds__(256) void k_attn(const bf16* __restrict__ qkvb,
        const float* __restrict__ bm, bf16* __restrict__ awin) {
    extern __shared__ bf16 sall[];   /* 12 mats x [64][40] */
    int win = blockIdx.x;
    int widx = win & 63;
    int tid = threadIdx.x;
    for (int i = tid; i < 3072; i += 256) {
        int rowid = i >> 2, c = (i & 3) * 8;
        int mat = rowid >> 6, row = rowid & 63;  /* mat = which*4 + head */
        uint4 val = make_uint4(0, 0, 0, 0);
        if (row < WSQ)
            val = *(const uint4*)(qkvb + ((size_t)win * 12 + mat) * (WSQ * HD) + row * HD + c);
        *(uint4*)(sall + (size_t)mat * 64 * ALD + row * ALD + c) = val;
    }
    __syncthreads();
    int warp = tid >> 5, lane = tid & 31;
    int head = warp >> 1, wm0 = (warp & 1) * 32;
    const bf16* Q = sall + (size_t)(0 + head) * 64 * ALD;
    const bf16* K = sall + (size_t)(4 + head) * 64 * ALD;
    const bf16* V = sall + (size_t)(8 + head) * 64 * ALD;

    /* QK^T: logits[2 mtiles][7 ntiles] */
    float qk[2][7][4];
    #pragma unroll
    for (int a = 0; a < 2; a++)
        #pragma unroll
        for (int b = 0; b < 7; b++)
            #pragma unroll
            for (int q = 0; q < 4; q++) qk[a][b][q] = 0.f;
    {
        uint32_t qf[2][2][4];
        #pragma unroll
        for (int mi = 0; mi < 2; mi++)
            #pragma unroll
            for (int ks = 0; ks < 2; ks++)
                load_afrag(qf[mi][ks], Q, ALD, wm0 + mi * 16, ks * 16, lane);
        #pragma unroll
        for (int nt = 0; nt < 7; nt++) {
            uint32_t t4[4];   /* non-trans on K rows -> B frags for both ksteps */
            ldsm4(t4, sptr(K + (nt * 8 + (lane & 7)) * ALD + ((lane >> 3) << 3)));
            uint32_t b0[2] = { t4[0], t4[1] }, b1[2] = { t4[2], t4[3] };
            #pragma unroll
            for (int mi = 0; mi < 2; mi++) {
                mma16816(qk[mi][nt], qf[mi][0], b0);
                mma16816(qk[mi][nt], qf[mi][1], b1);
            }
        }
    }
    /* scale + bias + mask */
    const float scale = 0.17677669529663687f;
    const float* bmh = bm + ((size_t)(widx * HEADS + head)) * WSQ * 56;
    #pragma unroll
    for (int mi = 0; mi < 2; mi++)
        #pragma unroll
        for (int h2 = 0; h2 < 2; h2++) {
            int i = wm0 + mi * 16 + (lane >> 2) + h2 * 8;
            #pragma unroll
            for (int nt = 0; nt < 7; nt++) {
                int j = nt * 8 + ((lane & 3) << 1);
                float2 bv = (i < WSQ) ? *(const float2*)(bmh + i * 56 + j)
                                      : make_float2(-1e30f, -1e30f);
                qk[mi][nt][h2*2]   = qk[mi][nt][h2*2]   * scale + bv.x;
                qk[mi][nt][h2*2+1] = qk[mi][nt][h2*2+1] * scale + bv.y;
            }
        }
    /* register softmax (rows span 4 lanes: shfl_xor 1,2) */
    #pragma unroll
    for (int mi = 0; mi < 2; mi++)
        #pragma unroll
        for (int h2 = 0; h2 < 2; h2++) {
            float mx = -1e30f;
            #pragma unroll
            for (int nt = 0; nt < 7; nt++)
                mx = fmaxf(mx, fmaxf(qk[mi][nt][h2*2], qk[mi][nt][h2*2+1]));
            mx = fmaxf(mx, __shfl_xor_sync(0xffffffffu, mx, 1));
            mx = fmaxf(mx, __shfl_xor_sync(0xffffffffu, mx, 2));
            float sum = 0.f;
            #pragma unroll
            for (int nt = 0; nt < 7; nt++) {
                float e0 = __expf(qk[mi][nt][h2*2]   - mx);
                float e1 = __expf(qk[mi][nt][h2*2+1] - mx);
                qk[mi][nt][h2*2] = e0; qk[mi][nt][h2*2+1] = e1;
                sum += e0 + e1;
            }
            sum += __shfl_xor_sync(0xffffffffu, sum, 1);
            sum += __shfl_xor_sync(0xffffffffu, sum, 2);
            float inv = 1.0f / sum;
            #pragma unroll
            for (int nt = 0; nt < 7; nt++) { qk[mi][nt][h2*2] *= inv; qk[mi][nt][h2*2+1] *= inv; }
        }
    /* PV: P (register A-frags) x V */
    float outa[2][4][4];
    #pragma unroll
    for (int a = 0; a < 2; a++)
        #pragma unroll
        for (int b = 0; b < 4; b++)
            #pragma unroll
            for (int q = 0; q < 4; q++) outa[a][b][q] = 0.f;
    #pragma unroll
    for (int kt = 0; kt < 4; kt++) {
        uint32_t vf[4][2];
        #pragma unroll
        for (int half = 0; half < 2; half++) {
            uint32_t t4[4];
            int q = lane >> 3, rr = lane & 7;
            ldsm4t(t4, sptr(V + (kt * 16 + rr + ((q & 1) << 3)) * ALD + half * 16 + ((q & 2) << 2)));
            vf[half*2][0]=t4[0]; vf[half*2][1]=t4[1]; vf[half*2+1][0]=t4[2]; vf[half*2+1][1]=t4[3];
        }
        #pragma unroll
        for (int mi = 0; mi < 2; mi++) {
            uint32_t pf[4];
            int n0 = kt * 2, n1 = kt * 2 + 1;
            pf[0] = pack_bf2(qk[mi][n0][0], qk[mi][n0][1]);
            pf[1] = pack_bf2(qk[mi][n0][2], qk[mi][n0][3]);
            if (n1 < 7) {
                pf[2] = pack_bf2(qk[mi][n1][0], qk[mi][n1][1]);
                pf[3] = pack_bf2(qk[mi][n1][2], qk[mi][n1][3]);
            } else { pf[2] = 0u; pf[3] = 0u; }
            #pragma unroll
            for (int dt = 0; dt < 4; dt++) mma16816(outa[mi][dt], pf, vf[dt]);
        }
    }
    #pragma unroll
    for (int mi = 0; mi < 2; mi++)
        #pragma unroll
        for (int h2 = 0; h2 < 2; h2++) {
            int i = wm0 + mi * 16 + (lane >> 2) + h2 * 8;
            if (i < WSQ) {
                size_t base = ((size_t)win * WSQ + i) * DIM + head * HD;
                #pragma unroll
                for (int dt = 0; dt < 4; dt++) {
                    int d = dt * 8 + ((lane & 3) << 1);
                    *(bf162*)(awin + base + d) =
                        __floats2bfloat162_rn(outa[mi][dt][h2*2], outa[mi][dt][h2*2+1]);
                }
            }
        }
}

/* ---------------- proj GEMM + reverse-shift + residuals + LN2 ----------- */
#define PLD 136
__global__ __launch_bounds__(256) void k_proj(const bf16* __restrict__ awin,
        const bf16* __restrict__ wpb, const float* __restrict__ proj_b,
        const float* __restrict__ x, const float* __restrict__ xs,
        const float* __restrict__ gate, const float* __restrict__ ln2g,
        const float* __restrict__ ln2b, float* __restrict__ x2,
        bf16* __restrict__ xnb) {
    extern __shared__ char smraw[];
    bf16* As = (bf16*)smraw;                       /* [64][136] */
    bf16* Bs = (bf16*)(smraw + 64 * PLD * 2);      /* [128][136] */
    float* so = (float*)smraw;                     /* [64][132] alias */
    int tid = threadIdx.x;
    int m0 = blockIdx.x * 64;
    for (int i = tid; i < 64 * 16; i += 256) {
        int r = i >> 4, c = i & 15;
        *(uint4*)(As + r * PLD + c * 8) = *(const uint4*)(awin + ((size_t)(m0 + r)) * DIM + c * 8);
    }
    for (int i = tid; i < 128 * 16; i += 256) {
        int r = i >> 4, c = i & 15;
        *(uint4*)(Bs + r * PLD + c * 8) = *(const uint4*)(wpb + (size_t)r * DIM + c * 8);
    }
    __syncthreads();
    int warp = tid >> 5, lane = tid & 31;
    int wm0 = (warp >> 2) * 32, wn0 = (warp & 3) * 32;
    float acc[2][4][4];
    #pragma unroll
    for (int a = 0; a < 2; a++)
        #pragma unroll
        for (int b = 0; b < 4; b++)
            #pragma unroll
            for (int q = 0; q < 4; q++) acc[a][b][q] = 0.f;
    #pragma unroll
    for (int ks = 0; ks < 8; ks++) {
        int k0 = ks * 16;
        uint32_t af[2][4];
        load_afrag(af[0], As, PLD, wm0,      k0, lane);
        load_afrag(af[1], As, PLD, wm0 + 16, k0, lane);
        uint32_t bfr[4][2];
        #pragma unroll
        for (int nt = 0; nt < 2; nt++) {
            uint32_t t4[4];
            load_bfrag2(t4, Bs, PLD, k0, wn0 + nt * 16, lane);
            bfr[nt*2][0]=t4[0]; bfr[nt*2][1]=t4[1]; bfr[nt*2+1][0]=t4[2]; bfr[nt*2+1][1]=t4[3];
        }
        #pragma unroll
        for (int mi = 0; mi < 2; mi++)
            #pragma unroll
            for (int ni = 0; ni < 4; ni++) mma16816(acc[mi][ni], af[mi], bfr[ni]);
    }
    __syncthreads();
    #pragma unroll
    for (int mi = 0; mi < 2; mi++)
        #pragma unroll
        for (int ni = 0; ni < 4; ni++)
            #pragma unroll
            for (int h2 = 0; h2 < 2; h2++) {
                int row = wm0 + mi * 16 + (lane >> 2) + h2 * 8;
                int col = wn0 + ni * 8 + ((lane & 3) << 1);
                so[row * 132 + col]     = acc[mi][ni][h2*2];
                so[row * 132 + col + 1] = acc[mi][ni][h2*2+1];
            }
    __syncthreads();
    /* per-row: residuals + LN2; warp handles 8 rows */
    for (int rr = 0; rr < 8; rr++) {
        int row = warp * 8 + rr;
        int m = m0 + row;
        int b;
        int dst = win_src_token(m, &b);
        float gt = gate[b];
        float v[4]; float ssum = 0.f;
        #pragma unroll
        for (int jj = 0; jj < 4; jj++) {
            int c = lane + jj * 32;
            size_t off = (size_t)dst * DIM + c;
            v[jj] = so[row * 132 + c] + proj_b[c] + x[off] + xs[off] * gt;
            ssum += v[jj];
        }
        #pragma unroll
        for (int o = 16; o; o >>= 1) ssum += __shfl_xor_sync(0xffffffffu, ssum, o);
        float mu = ssum * (1.0f / DIM);
        float s2 = 0.f;
        #pragma unroll
        for (int jj = 0; jj < 4; jj++) { float d = v[jj] - mu; s2 += d * d; }
        #pragma unroll
        for (int o = 16; o; o >>= 1) s2 += __shfl_xor_sync(0xffffffffu, s2, o);
        float rsig = rsqrtf(s2 * (1.0f / DIM) + 1e-5f);
        #pragma unroll
        for (int jj = 0; jj < 4; jj++) {
            int c = lane + jj * 32;
            size_t off = (size_t)dst * DIM + c;
            x2[off]  = v[jj];
            xnb[off] = __float2bfloat16((v[jj] - mu) * rsig * ln2g[c] + ln2b[c]);
        }
    }
}

/* ---------------- fused MLP (bf16 mma, gelu in regs) --------------------- */
#define XLD 136
#define W1LD 72
#define W2LD 136
#define HLD 72
__global__ __launch_bounds__(256) void k_mlp(const bf16* __restrict__ xnb,
        const bf16* __restrict__ w1b, const float* __restrict__ b1,
        const bf16* __restrict__ w2b, const float* __restrict__ b2,
        const float* __restrict__ x2, float* __restrict__ out) {
    extern __shared__ bf16 smm[];
    bf16* sx  = smm;                        /* [128][136] */
    bf16* sw1 = sx  + 128 * XLD;            /* [128][72]  */
    bf16* sw2 = sw1 + 128 * W1LD;           /* [64][136]  */
    bf16* sh  = sw2 + 64 * W2LD;            /* [128][72]  */
    int tid = threadIdx.x;
    size_t t0 = (size_t)blockIdx.x * 128;
    for (int i = tid; i < 128 * 16; i += 256) {
        int r = i >> 4, c = i & 15;
        *(uint4*)(sx + r * XLD + c * 8) = *(const uint4*)(xnb + (t0 + r) * DIM + c * 8);
    }
    int warp = tid >> 5, lane = tid & 31;
    int wm0 = (warp & 3) * 32, wn0 = (warp >> 2) * 64, wn1 = (warp >> 2) * 32;
    float oacc[2][8][4];
    #pragma unroll
    for (int a = 0; a < 2; a++)
        #pragma unroll
        for (int b = 0; b < 8; b++)
            #pragma unroll
            for (int q = 0; q < 4; q++) oacc[a][b][q] = 0.f;
    for (int cc = 0; cc < 8; cc++) {
        __syncthreads();
        for (int i = tid; i < 128 * 8; i += 256) {
            int r = i >> 3, c = i & 7;
            *(uint4*)(sw1 + r * W1LD + c * 8) = *(const uint4*)(w1b + (size_t)r * NMLP + cc * 64 + c * 8);
        }
        for (int i = tid; i < 64 * 16; i += 256) {
            int r = i >> 4, c = i & 15;
            *(uint4*)(sw2 + r * W2LD + c * 8) = *(const uint4*)(w2b + ((size_t)cc * 64 + r) * DIM + c * 8);
        }
        __syncthreads();
        float hacc[2][4][4];
        #pragma unroll
        for (int a = 0; a < 2; a++)
            #pragma unroll
            for (int b = 0; b < 4; b++)
                #pragma unroll
                for (int q = 0; q < 4; q++) hacc[a][b][q] = 0.f;
        #pragma unroll
        for (int ks = 0; ks < 8; ks++) {
            int k0 = ks * 16;
            uint32_t af[2][4];
            load_afrag(af[0], sx, XLD, wm0,      k0, lane);
            load_afrag(af[1], sx, XLD, wm0 + 16, k0, lane);
            uint32_t bfr[4][2];
            #pragma unroll
            for (int nt = 0; nt < 2; nt++) {
                uint32_t t4[4];
                load_bfrag2(t4, sw1, W1LD, k0, wn1 + nt * 16, lane);
                bfr[nt*2][0]=t4[0]; bfr[nt*2][1]=t4[1]; bfr[nt*2+1][0]=t4[2]; bfr[nt*2+1][1]=t4[3];
            }
            #pragma unroll
            for (int mi = 0; mi < 2; mi++)
                #pragma unroll
                for (int ni = 0; ni < 4; ni++) mma16816(hacc[mi][ni], af[mi], bfr[ni]);
        }
        #pragma unroll
        for (int mi = 0; mi < 2; mi++)
            #pragma unroll
            for (int ni = 0; ni < 4; ni++)
                #pragma unroll
                for (int h2 = 0; h2 < 2; h2++) {
                    int row = wm0 + mi * 16 + (lane >> 2) + h2 * 8;
                    int col = wn1 + ni * 8 + ((lane & 3) << 1);
                    float v0 = hacc[mi][ni][h2*2]   + b1[cc * 64 + col];
                    float v1 = hacc[mi][ni][h2*2+1] + b1[cc * 64 + col + 1];
                    v0 = 0.5f * v0 * (1.0f + erff(v0 * 0.70710678118654752f));
                    v1 = 0.5f * v1 * (1.0f + erff(v1 * 0.70710678118654752f));
                    *(bf162*)(sh + row * HLD + col) = __floats2bfloat162_rn(v0, v1);
                }
        __syncthreads();
        #pragma unroll
        for (int ks = 0; ks < 4; ks++) {
            int k0 = ks * 16;
            uint32_t af[2][4];
            load_afrag(af[0], sh, HLD, wm0,      k0, lane);
            load_afrag(af[1], sh, HLD, wm0 + 16, k0, lane);
            uint32_t bfr[8][2];
            #pragma unroll
            for (int nt = 0; nt < 4; nt++) {
                uint32_t t4[4];
                load_bfrag2(t4, sw2, W2LD, k0, wn0 + nt * 16, lane);
                bfr[nt*2][0]=t4[0]; bfr[nt*2][1]=t4[1]; bfr[nt*2+1][0]=t4[2]; bfr[nt*2+1][1]=t4[3];
            }
            #pragma unroll
            for (int mi = 0; mi < 2; mi++)
                #pragma unroll
                for (int ni = 0; ni < 8; ni++) mma16816(oacc[mi][ni], af[mi], bfr[ni]);
        }
    }
    #pragma unroll
    for (int mi = 0; mi < 2; mi++)
        #pragma unroll
        for (int ni = 0; ni < 8; ni++)
            #pragma unroll
            for (int h2 = 0; h2 < 2; h2++) {
                int row = wm0 + mi * 16 + (lane >> 2) + h2 * 8;
                int col = wn0 + ni * 8 + ((lane & 3) << 1);
                size_t off = (t0 + row) * DIM + col;
                float2 r;
                r.x = x2[off]     + oacc[mi][ni][h2*2]   + b2[col];
                r.y = x2[off + 1] + oacc[mi][ni][h2*2+1] + b2[col + 1];
                *(float2*)(out + off) = r;
            }
}

/* ------------------------------- launch --------------------------------- */
extern "C" void kernel_launch(void* const* d_in, const int* in_sizes, int n_in,
                              void* d_out, int out_size) {
    const float* x        = (const float*)d_in[0];
    const float* ln1_g    = (const float*)d_in[1];
    const float* ln1_b    = (const float*)d_in[2];
    const float* eca_w    = (const float*)d_in[3];
    const float* qkv_w    = (const float*)d_in[4];
    const float* qkv_b    = (const float*)d_in[5];
    const float* rel_tbl  = (const float*)d_in[6];
    const float* proj_w   = (const float*)d_in[7];
    const float* proj_b   = (const float*)d_in[8];
    const float* ln2_g    = (const float*)d_in[9];
    const float* ln2_b    = (const float*)d_in[10];
    const float* mlp_w1   = (const float*)d_in[11];
    const float* mlp_b1   = (const float*)d_in[12];
    const float* mlp_w2   = (const float*)d_in[13];
    const float* mlp_b2   = (const float*)d_in[14];
    const float* attn_msk = (const float*)d_in[15];
    const int*   rel_idx  = (const int*)d_in[16];
    float* out = (float*)d_out;

    float *xs_p, *gate_p, *x2_p, *bm_p;
    bf16 *xsb_p, *qkvb_p, *awinb_p, *xnb_p, *wq_p, *wp_p, *w1_p, *w2_p;
    cudaGetSymbolAddress((void**)&xs_p,    g_xs);
    cudaGetSymbolAddress((void**)&xsb_p,   g_xsb);
    cudaGetSymbolAddress((void**)&gate_p,  g_gate);
    cudaGetSymbolAddress((void**)&qkvb_p,  g_qkvb);
    cudaGetSymbolAddress((void**)&awinb_p, g_awinb);
    cudaGetSymbolAddress((void**)&x2_p,    g_x2);
    cudaGetSymbolAddress((void**)&xnb_p,   g_xnb);
    cudaGetSymbolAddress((void**)&wq_p,    g_wqb);
    cudaGetSymbolAddress((void**)&wp_p,    g_wpb);
    cudaGetSymbolAddress((void**)&w1_p,    g_w1b);
    cudaGetSymbolAddress((void**)&w2_p,    g_w2b);
    cudaGetSymbolAddress((void**)&bm_p,    g_bm);

    const int SM_QKV  = 2 * 128 * QLD * 2;                     /* 69632 */
    const int SM_ATT  = 12 * 64 * ALD * 2;                     /* 61440 */
    const int SM_PROJ = (64 + 128) * PLD * 2;                  /* 52224 */
    const int SM_MLP  = (128*XLD + 128*W1LD + 64*W2LD + 128*HLD) * 2; /* 89088 */
    cudaFuncSetAttribute(k_qkv,  cudaFuncAttributeMaxDynamicSharedMemorySize, SM_QKV);
    cudaFuncSetAttribute(k_attn, cudaFuncAttributeMaxDynamicSharedMemorySize, SM_ATT);
    cudaFuncSetAttribute(k_proj, cudaFuncAttributeMaxDynamicSharedMemorySize, SM_PROJ);
    cudaFuncSetAttribute(k_mlp,  cudaFuncAttributeMaxDynamicSharedMemorySize, SM_MLP);

    k_convw<<<256, 256>>>(qkv_w, proj_w, mlp_w1, mlp_w2, wq_p, wp_p, w1_p, w2_p);
    k_bm   <<<(NWIN*HEADS*WSQ*56 + 255) / 256, 256>>>(rel_tbl, rel_idx, attn_msk, bm_p);
    k_ln1  <<<M_TOK, 128>>>(x, ln1_g, ln1_b, xs_p, xsb_p);
    k_gate <<<BATCH, 512>>>(xs_p, eca_w, gate_p);
    k_qkv  <<<dim3(M_TOK / 128, 3), 256, SM_QKV>>>(xsb_p, wq_p, qkv_b, qkvb_p);
    k_attn <<<TOTWIN, 256, SM_ATT>>>(qkvb_p, bm_p, awinb_p);
    k_proj <<<M_TOK / 64, 256, SM_PROJ>>>(awinb_p, wp_p, proj_b, x, xs_p, gate_p,
                                          ln2_g, ln2_b, x2_p, xnb_p);
    k_mlp  <<<M_TOK / 128, 256, SM_MLP>>>(xnb_p, w1_p, mlp_b1, w2_p, mlp_b2, x2_p, out);
}